// round 11
// baseline (speedup 1.0000x reference)
#include <cuda_runtime.h>
#include <math.h>

#define EPS_F 1e-6f
#define NCOL 64
#define LSTEP 63

__device__ __forceinline__ float clip01(float v) {
    return fminf(fmaxf(v, EPS_F), 1.0f);
}

// log2 term for the fast path. Reference clips x to [EPS, 1]; the input domain
// is [0,1) so only the EPS floor can bind.
__device__ __forceinline__ float lg2c(float v) {
    return __log2f(fmaxf(v, EPS_F));
}

__device__ __forceinline__ float dot8_log(const float4& v0, const float4& v1,
                                          const float4& c0, const float4& c1) {
    float s;
    s = c0.x * lg2c(v0.x);
    s = fmaf(c0.y, lg2c(v0.y), s);
    s = fmaf(c0.z, lg2c(v0.z), s);
    s = fmaf(c0.w, lg2c(v0.w), s);
    s = fmaf(c1.x, lg2c(v1.x), s);
    s = fmaf(c1.y, lg2c(v1.y), s);
    s = fmaf(c1.z, lg2c(v1.z), s);
    s = fmaf(c1.w, lg2c(v1.w), s);
    return s;
}

// Generic single aggregation step (slow path, semantics-exact), params passed in
__device__ float aggregate_step(float acc, float right,
                                float r, float wa, float wn, int geo) {
    float acc_c = clip01(acc);
    float rc    = clip01(right);
    if (geo) return powf(acc_c, wa) * powf(rc, wn);
    return powf(wa * powf(acc_c, r) + wn * powf(rc, r), 1.0f / r);
}

// Single kernel, zero cross-block dependencies.
//  * Every thread issues its 4 independent x-LDG.128s FIRST (proven R5/R9
//    pattern: 8 lanes/row, 2 rows/thread (i, i+B/2), lane s loads float4
//    index s and s+8 — each warp-LDG covers 4 fully-contiguous 128B lines).
//  * Warp 0 of each block then computes ALL parameters alone (2 indices per
//    lane): shfl min/max reduce + per-element math + 5-step shfl suffix-
//    product scan over lane-pairs -> s_coef in smem. ~200 instructions,
//    fully parallel, no serial loop.
//  * One __syncthreads. Its wait (= warp-0 setup time) overlaps the DRAM
//    latency of the already-issued x loads.
__global__ void __launch_bounds__(256)
vln_kernel(const float* __restrict__ x,
           const float* __restrict__ a_raw,
           const float* __restrict__ w_raw,
           float* __restrict__ out, int B) {
    __shared__ __align__(16) float s_coef[NCOL];
    __shared__ float s_a[LSTEP], s_r[LSTEP], s_wa[LSTEP], s_wn[LSTEP];
    __shared__ int   s_geo[LSTEP];
    __shared__ int   s_allgeo;

    const int t    = threadIdx.x;
    const int gtid = blockIdx.x * blockDim.x + t;
    const int half = B >> 1;
    const int i    = gtid >> 3;
    const int s    = gtid & 7;

    const bool active = (i < half);
    const int  rowA   = active ? i : 0;
    const int  rowB   = active ? (i + half) : 0;

    const float4* pa = reinterpret_cast<const float4*>(x + (size_t)rowA * NCOL);
    const float4* pb = reinterpret_cast<const float4*>(x + (size_t)rowB * NCOL);

    // ---- 1) front-batched independent x loads (MLP=4) ----------------------
    float4 xa0 = __ldg(pa + s);
    float4 xa1 = __ldg(pa + s + 8);
    float4 xb0 = __ldg(pb + s);
    float4 xb1 = __ldg(pb + s + 8);

    // ---- 2) warp 0 computes the parameters (overlaps x-load latency) -------
    if (t < 32) {
        const int  L  = t;
        const int  k0 = 2 * L;
        const int  k1 = 2 * L + 1;
        const bool v1 = (k1 < LSTEP);   // only lane 31's k1 is invalid

        float w0  = __ldg(w_raw + k0);
        float w1  = v1 ? __ldg(w_raw + k1) : 0.0f;
        float ar0 = __ldg(a_raw + k0);
        float ar1 = v1 ? __ldg(a_raw + k1) : 0.0f;

        // block-wide (warp-wide) min/max of w
        float lo = fminf(w0, v1 ? w1 :  3.0e38f);
        float hi = fmaxf(w0, v1 ? w1 : -3.0e38f);
#pragma unroll
        for (int d = 16; d; d >>= 1) {
            lo = fminf(lo, __shfl_xor_sync(0xFFFFFFFFu, lo, d));
            hi = fmaxf(hi, __shfl_xor_sync(0xFFFFFFFFu, hi, d));
        }
        const float wmin  = lo;
        const float denom = fmaxf(hi - lo, 1e-8f);

        // per-element parameters for k0 and k1
        float aa0 = 3.0f / (1.0f + expf(-ar0)) - 1.0f;
        float ac0 = fminf(fmaxf(aa0, EPS_F), 1.0f - EPS_F);
        float rr0 = (1.0f - 2.0f * ac0) / (ac0 * (1.0f - ac0));
        int   ge0 = fabsf(rr0) < 0.001f;
        float wn0 = fminf(fmaxf((w0 - wmin) / denom, 0.0f), 1.0f);
        float wa0 = 1.0f - wn0;

        float aa1 = 3.0f / (1.0f + expf(-ar1)) - 1.0f;
        float ac1 = fminf(fmaxf(aa1, EPS_F), 1.0f - EPS_F);
        float rr1 = (1.0f - 2.0f * ac1) / (ac1 * (1.0f - ac1));
        int   ge1 = fabsf(rr1) < 0.001f;
        float wn1 = fminf(fmaxf((w1 - wmin) / denom, 0.0f), 1.0f);
        float wa1 = 1.0f - wn1;
        if (!v1) { wa1 = 1.0f; wn1 = 0.0f; ge1 = 1; }   // identity for k=63

        int allg = __all_sync(0xFFFFFFFFu, ge0 && ge1);

        // slow-path tables
        s_a[k0] = aa0; s_r[k0] = rr0; s_wa[k0] = wa0; s_wn[k0] = wn0; s_geo[k0] = ge0;
        if (v1) { s_a[k1] = aa1; s_r[k1] = rr1; s_wa[k1] = wa1; s_wn[k1] = wn1; s_geo[k1] = ge1; }

        // suffix products: pair product, then 5-step inclusive suffix scan
        float S = wa0 * wa1;                       // p_L
#pragma unroll
        for (int d = 1; d < 32; d <<= 1) {
            float v = __shfl_down_sync(0xFFFFFFFFu, S, d);
            if (L + d < 32) S *= v;
        }
        float Sd = __shfl_down_sync(0xFFFFFFFFu, S, 1);
        float X  = (L == 31) ? 1.0f : Sd;          // X_L = prod of pairs j > L

        float Ek1 = X;                              // E_{2L+1}
        float Ek0 = wa1 * X;                        // E_{2L}

        // coefficients: c_{k+1} = wnew_k * E_k;  c_0 = wacc_0 * E_0
        s_coef[k0 + 1] = wn0 * Ek0;
        if (v1) s_coef[k1 + 1] = wn1 * Ek1;
        if (L == 0) { s_coef[0] = wa0 * Ek0; s_allgeo = allg; }
    }
    __syncthreads();

    // ---- 3) main computation ----------------------------------------------
    if (!active) return;

    if (s_allgeo) {
        const float4* pc = reinterpret_cast<const float4*>(s_coef);
        float4 c0 = pc[s];
        float4 c1 = pc[s + 8];

        float sa = dot8_log(xa0, xa1, c0, c1);
        float sb = dot8_log(xb0, xb1, c0, c1);

        sa += __shfl_xor_sync(0xFFFFFFFFu, sa, 4);
        sb += __shfl_xor_sync(0xFFFFFFFFu, sb, 4);
        sa += __shfl_xor_sync(0xFFFFFFFFu, sa, 2);
        sb += __shfl_xor_sync(0xFFFFFFFFu, sb, 2);
        sa += __shfl_xor_sync(0xFFFFFFFFu, sa, 1);
        sb += __shfl_xor_sync(0xFFFFFFFFu, sb, 1);

        if (s == 0) {
            out[rowA] = exp2f(sa);
            out[rowB] = exp2f(sb);
        }
    } else {
        // Generic sequential path (unused for these inputs): leader walks rows.
        if (s == 0) {
            int rows[2] = {rowA, rowB};
#pragma unroll
            for (int q = 0; q < 2; q++) {
                const float* xr = x + (size_t)rows[q] * NCOL;
                float acc = aggregate_step(xr[0], xr[1], s_r[0], s_wa[0], s_wn[0], s_geo[0]);
                for (int k = 1; k < LSTEP; k++) {
                    float z = aggregate_step(acc, xr[k + 1], s_r[k], s_wa[k], s_wn[k], s_geo[k]);
                    if (isnan(z)) z = s_a[k];
                    acc = z;
                }
                out[rows[q]] = acc;
            }
        }
    }
}

extern "C" void kernel_launch(void* const* d_in, const int* in_sizes, int n_in,
                              void* d_out, int out_size) {
    const float* x     = (const float*)d_in[0];
    const float* a_raw = (const float*)d_in[1];
    const float* w_raw = (const float*)d_in[2];
    float* out = (float*)d_out;

    int B = in_sizes[0] / NCOL;   // B is even for this problem (524288)

    long long total_threads = ((long long)B / 2) * 8;
    int threads = 256;
    int blocks  = (int)((total_threads + threads - 1) / threads);

    vln_kernel<<<blocks, threads>>>(x, a_raw, w_raw, out, B);
}

// round 12
// speedup vs baseline: 1.0703x; 1.0703x over previous
#include <cuda_runtime.h>
#include <math.h>

#define EPS_F 1e-6f
#define NCOL 64
#define LSTEP 63

__device__ __forceinline__ float clip01(float v) {
    return fminf(fmaxf(v, EPS_F), 1.0f);
}

// log2 term for the fast path. Reference clips x to [EPS, 1]; the input domain
// is [0,1) so only the EPS floor can bind.
__device__ __forceinline__ float lg2c(float v) {
    return __log2f(fmaxf(v, EPS_F));
}

__device__ __forceinline__ float dot8_log(const float4& v0, const float4& v1,
                                          const float4& c0, const float4& c1) {
    float s;
    s = c0.x * lg2c(v0.x);
    s = fmaf(c0.y, lg2c(v0.y), s);
    s = fmaf(c0.z, lg2c(v0.z), s);
    s = fmaf(c0.w, lg2c(v0.w), s);
    s = fmaf(c1.x, lg2c(v1.x), s);
    s = fmaf(c1.y, lg2c(v1.y), s);
    s = fmaf(c1.z, lg2c(v1.z), s);
    s = fmaf(c1.w, lg2c(v1.w), s);
    return s;
}

// Generic single aggregation step (slow path, semantics-exact), params passed in
__device__ float aggregate_step(float acc, float right,
                                float r, float wa, float wn, int geo) {
    float acc_c = clip01(acc);
    float rc    = clip01(right);
    if (geo) return powf(acc_c, wa) * powf(rc, wn);
    return powf(wa * powf(acc_c, r) + wn * powf(rc, r), 1.0f / r);
}

// Single kernel, zero cross-block dependencies.
//  * Every thread issues its 4 independent x-LDG.128s FIRST (proven pattern:
//    8 lanes/row, 2 rows/thread (i, i+B/2), lane s loads float4 index s and
//    s+8 — each warp-LDG covers 4 fully-contiguous 128B lines; MLP=4).
//  * Warp 0 of each block computes ALL parameters alone (2 steps per lane):
//    shfl min/max reduce + per-step math + 5-step shfl suffix-product scan
//    over lane-pairs -> s_coef in smem. No serial loop, no cross-block traffic.
//  * One __syncthreads; its wait overlaps the in-flight x-load DRAM latency.
//  * __launch_bounds__(256, 8) caps regs at 32: the setup branch spills to
//    L1-cached local (touched once per block by warp 0 only), keeping the
//    main path at the proven 32-reg / high-occupancy profile (R10 evidence).
__global__ void __launch_bounds__(256, 8)
vln_kernel(const float* __restrict__ x,
           const float* __restrict__ a_raw,
           const float* __restrict__ w_raw,
           float* __restrict__ out, int B) {
    __shared__ __align__(16) float s_coef[NCOL];
    __shared__ float s_a[LSTEP], s_r[LSTEP], s_wa[LSTEP], s_wn[LSTEP];
    __shared__ int   s_geo[LSTEP];
    __shared__ int   s_allgeo;

    const int t    = threadIdx.x;
    const int gtid = blockIdx.x * blockDim.x + t;
    const int half = B >> 1;
    const int i    = gtid >> 3;
    const int s    = gtid & 7;

    const bool active = (i < half);
    const int  rowA   = active ? i : 0;
    const int  rowB   = active ? (i + half) : 0;

    const float4* pa = reinterpret_cast<const float4*>(x + (size_t)rowA * NCOL);
    const float4* pb = reinterpret_cast<const float4*>(x + (size_t)rowB * NCOL);

    // ---- 1) front-batched independent x loads (MLP=4) ----------------------
    float4 xa0 = __ldg(pa + s);
    float4 xa1 = __ldg(pa + s + 8);
    float4 xb0 = __ldg(pb + s);
    float4 xb1 = __ldg(pb + s + 8);

    // ---- 2) warp 0 computes the parameters (overlaps x-load latency) -------
    if (t < 32) {
        const int  L  = t;
        const int  k0 = 2 * L;
        const int  k1 = 2 * L + 1;
        const bool v1 = (k1 < LSTEP);   // only lane 31's k1 is invalid

        float w0 = __ldg(w_raw + k0);
        float w1 = v1 ? __ldg(w_raw + k1) : 0.0f;

        // warp-wide min/max of w
        float lo = fminf(w0, v1 ? w1 :  3.0e38f);
        float hi = fmaxf(w0, v1 ? w1 : -3.0e38f);
#pragma unroll
        for (int d = 16; d; d >>= 1) {
            lo = fminf(lo, __shfl_xor_sync(0xFFFFFFFFu, lo, d));
            hi = fmaxf(hi, __shfl_xor_sync(0xFFFFFFFFu, hi, d));
        }
        const float wmin  = lo;
        const float denom = fmaxf(hi - lo, 1e-8f);

        // step k0 (compute, store, release registers)
        float wn0, wa0;
        int   ge0;
        {
            float ar = __ldg(a_raw + k0);
            float a  = 3.0f / (1.0f + expf(-ar)) - 1.0f;
            float ac = fminf(fmaxf(a, EPS_F), 1.0f - EPS_F);
            float r  = (1.0f - 2.0f * ac) / (ac * (1.0f - ac));
            ge0 = fabsf(r) < 0.001f;
            wn0 = fminf(fmaxf((w0 - wmin) / denom, 0.0f), 1.0f);
            wa0 = 1.0f - wn0;
            s_a[k0] = a; s_r[k0] = r; s_wa[k0] = wa0; s_wn[k0] = wn0; s_geo[k0] = ge0;
        }

        // step k1 (identity for the padded slot at k=63)
        float wn1 = 0.0f, wa1 = 1.0f;
        int   ge1 = 1;
        if (v1) {
            float ar = __ldg(a_raw + k1);
            float a  = 3.0f / (1.0f + expf(-ar)) - 1.0f;
            float ac = fminf(fmaxf(a, EPS_F), 1.0f - EPS_F);
            float r  = (1.0f - 2.0f * ac) / (ac * (1.0f - ac));
            ge1 = fabsf(r) < 0.001f;
            wn1 = fminf(fmaxf((w1 - wmin) / denom, 0.0f), 1.0f);
            wa1 = 1.0f - wn1;
            s_a[k1] = a; s_r[k1] = r; s_wa[k1] = wa1; s_wn[k1] = wn1; s_geo[k1] = ge1;
        }

        int allg = __all_sync(0xFFFFFFFFu, ge0 && ge1);

        // suffix products: pair product, then 5-step inclusive suffix scan
        float S = wa0 * wa1;                       // p_L
#pragma unroll
        for (int d = 1; d < 32; d <<= 1) {
            float v = __shfl_down_sync(0xFFFFFFFFu, S, d);
            if (L + d < 32) S *= v;
        }
        float Sd = __shfl_down_sync(0xFFFFFFFFu, S, 1);
        float X  = (L == 31) ? 1.0f : Sd;          // prod of pairs j > L

        float Ek1 = X;                              // E_{2L+1}
        float Ek0 = wa1 * X;                        // E_{2L}

        // coefficients: c_{k+1} = wnew_k * E_k;  c_0 = wacc_0 * E_0
        s_coef[k0 + 1] = wn0 * Ek0;
        if (v1) s_coef[k1 + 1] = wn1 * Ek1;
        if (L == 0) { s_coef[0] = wa0 * Ek0; s_allgeo = allg; }
    }
    __syncthreads();

    // ---- 3) main computation ----------------------------------------------
    if (!active) return;

    if (s_allgeo) {
        const float4* pc = reinterpret_cast<const float4*>(s_coef);
        float4 c0 = pc[s];
        float4 c1 = pc[s + 8];

        float sa = dot8_log(xa0, xa1, c0, c1);
        float sb = dot8_log(xb0, xb1, c0, c1);

        sa += __shfl_xor_sync(0xFFFFFFFFu, sa, 4);
        sb += __shfl_xor_sync(0xFFFFFFFFu, sb, 4);
        sa += __shfl_xor_sync(0xFFFFFFFFu, sa, 2);
        sb += __shfl_xor_sync(0xFFFFFFFFu, sb, 2);
        sa += __shfl_xor_sync(0xFFFFFFFFu, sa, 1);
        sb += __shfl_xor_sync(0xFFFFFFFFu, sb, 1);

        if (s == 0) {
            out[rowA] = exp2f(sa);
            out[rowB] = exp2f(sb);
        }
    } else {
        // Generic sequential path (unused for these inputs): leader walks rows.
        if (s == 0) {
            int rows[2] = {rowA, rowB};
#pragma unroll
            for (int q = 0; q < 2; q++) {
                const float* xr = x + (size_t)rows[q] * NCOL;
                float acc = aggregate_step(xr[0], xr[1], s_r[0], s_wa[0], s_wn[0], s_geo[0]);
                for (int k = 1; k < LSTEP; k++) {
                    float z = aggregate_step(acc, xr[k + 1], s_r[k], s_wa[k], s_wn[k], s_geo[k]);
                    if (isnan(z)) z = s_a[k];
                    acc = z;
                }
                out[rows[q]] = acc;
            }
        }
    }
}

extern "C" void kernel_launch(void* const* d_in, const int* in_sizes, int n_in,
                              void* d_out, int out_size) {
    const float* x     = (const float*)d_in[0];
    const float* a_raw = (const float*)d_in[1];
    const float* w_raw = (const float*)d_in[2];
    float* out = (float*)d_out;

    int B = in_sizes[0] / NCOL;   // B is even for this problem (524288)

    long long total_threads = ((long long)B / 2) * 8;
    int threads = 256;
    int blocks  = (int)((total_threads + threads - 1) / threads);

    vln_kernel<<<blocks, threads>>>(x, a_raw, w_raw, out, B);
}

// round 13
// speedup vs baseline: 1.1404x; 1.0655x over previous
#include <cuda_runtime.h>
#include <math.h>

#define EPS_F 1e-6f
#define NCOL 64
#define LSTEP 63

// Per-launch derived parameters (computed on device by setup_kernel).
__device__ __align__(16) float g_coef[NCOL];  // log-domain coefficients (geo fast path)
__device__ int   g_all_geo;                   // 1 if every step is the geometric branch
__device__ float g_a[LSTEP];                  // a_vec (NaN replacement value)
__device__ float g_r[LSTEP];                  // power-mean exponent r
__device__ float g_wacc[LSTEP];
__device__ float g_wnew[LSTEP];
__device__ int   g_geo[LSTEP];                // per-step geo flag (generic path)

// Fully parallel 64-thread setup; triggers programmatic launch of the main
// grid immediately so main's blocks ramp up and prefetch x while this runs.
__global__ void vln_setup_kernel(const float* __restrict__ a_raw,
                                 const float* __restrict__ w_raw) {
#if __CUDA_ARCH__ >= 900
    cudaTriggerProgrammaticLaunchCompletion();
#endif
    __shared__ float s_mn[2], s_mx[2], s_S32;

    const int  t    = threadIdx.x;
    const int  lane = t & 31;
    const int  wid  = t >> 5;
    const bool pt   = (t < LSTEP);

    float w  = pt ? __ldg(w_raw + t) : 0.0f;
    float ar = pt ? __ldg(a_raw + t) : 0.0f;

    // warp min/max reduce (identities for t=63)
    {
        float lo = pt ? w :  3.0e38f;
        float hi = pt ? w : -3.0e38f;
#pragma unroll
        for (int d = 16; d; d >>= 1) {
            lo = fminf(lo, __shfl_xor_sync(0xFFFFFFFFu, lo, d));
            hi = fmaxf(hi, __shfl_xor_sync(0xFFFFFFFFu, hi, d));
        }
        if (lane == 0) { s_mn[wid] = lo; s_mx[wid] = hi; }
    }
    __syncthreads();

    float wnv = 0.0f, wav = 1.0f;
    int geov = 1;
    if (pt) {
        float wmin  = fminf(s_mn[0], s_mn[1]);
        float denom = fmaxf(fmaxf(s_mx[0], s_mx[1]) - wmin, 1e-8f);
        float a   = 3.0f / (1.0f + expf(-ar)) - 1.0f;
        float a_c = fminf(fmaxf(a, EPS_F), 1.0f - EPS_F);
        float r   = (1.0f - 2.0f * a_c) / (a_c * (1.0f - a_c));
        geov = fabsf(r) < 0.001f;
        wnv  = fminf(fmaxf((w - wmin) / denom, 0.0f), 1.0f);
        wav  = 1.0f - wnv;
        g_a[t]    = a;
        g_r[t]    = r;
        g_wnew[t] = wnv;
        g_wacc[t] = wav;
        g_geo[t]  = geov;
    }

    // inclusive suffix-product scan of wacc within each warp (t=63 -> 1)
    float S = pt ? wav : 1.0f;
#pragma unroll
    for (int d = 1; d < 32; d <<= 1) {
        float v = __shfl_down_sync(0xFFFFFFFFu, S, d);
        if (lane + d < 32) S *= v;
    }
    if (wid == 1 && lane == 0) s_S32 = S;   // prod_{32..62}

    int allgeo = __syncthreads_and(pt ? geov : 1);
    if (t == 0) g_all_geo = allgeo;

    // exclusive suffix product E_t = prod_{i>t} wacc_i, then coefficients
    {
        float E;
        if (wid == 0) {
            float S32 = s_S32;
            S *= S32;                                 // full inclusive suffix
            E = __shfl_down_sync(0xFFFFFFFFu, S, 1);
            if (lane == 31) E = S32;                  // E_31 = prod_{32..62}
        } else {
            E = __shfl_down_sync(0xFFFFFFFFu, S, 1);
            if (lane == 31) E = 1.0f;                 // t=63 unused
        }
        if (pt) {
            g_coef[t + 1] = wnv * E;                  // c_{t+1} = wnew_t * P[t+1]
            if (t == 0) g_coef[0] = wav * E;          // c_0 = wacc_0 * P[1]
        }
    }
}

__device__ __forceinline__ float clip01(float v) {
    return fminf(fmaxf(v, EPS_F), 1.0f);
}

// log2 term for the fast path. Reference clips x to [EPS, 1]; the input domain
// is [0,1) so only the EPS floor can bind.
__device__ __forceinline__ float lg2c(float v) {
    return __log2f(fmaxf(v, EPS_F));
}

// Generic single aggregation step (slow path, semantics-exact)
__device__ float aggregate_step(float acc, float right, int i) {
    float acc_c = clip01(acc);
    float rc    = clip01(right);
    if (g_geo[i]) {
        return powf(acc_c, g_wacc[i]) * powf(rc, g_wnew[i]);
    }
    float r = g_r[i];
    return powf(g_wacc[i] * powf(acc_c, r) + g_wnew[i] * powf(rc, r), 1.0f / r);
}

__device__ __forceinline__ float dot8_log(const float4& v0, const float4& v1,
                                          const float4& c0, const float4& c1) {
    float s;
    s = c0.x * lg2c(v0.x);
    s = fmaf(c0.y, lg2c(v0.y), s);
    s = fmaf(c0.z, lg2c(v0.z), s);
    s = fmaf(c0.w, lg2c(v0.w), s);
    s = fmaf(c1.x, lg2c(v1.x), s);
    s = fmaf(c1.y, lg2c(v1.y), s);
    s = fmaf(c1.z, lg2c(v1.z), s);
    s = fmaf(c1.w, lg2c(v1.w), s);
    return s;
}

// 8 lanes per row, 2 ADJACENT rows per thread (2i, 2i+1): each warp's 8
// front-batched LDG.128s cover one fully-contiguous 2KB span (rows 8w..8w+8)
// — a single DRAM stream per warp (vs two streams 64MB apart before), halving
// concurrent-stream count chip-wide and maximizing open-page hits. MLP=4.
// x-loads are issued BEFORE the PDL grid sync so setup + launch gap hide
// under them. Output pair becomes one float2 store.
__global__ void __launch_bounds__(256)
vln_main_kernel(const float* __restrict__ x, float* __restrict__ out, int B) {
    int gtid = blockIdx.x * blockDim.x + threadIdx.x;
    int half = B >> 1;
    int i    = gtid >> 3;
    int s    = gtid & 7;

    bool active = (i < half);
    int rowA = active ? (2 * i)     : 0;
    int rowB = active ? (2 * i + 1) : 0;

    const float4* pa = reinterpret_cast<const float4*>(x + (size_t)rowA * NCOL);
    const float4* pb = reinterpret_cast<const float4*>(x + (size_t)rowB * NCOL);

    // Front-batched independent loads (MLP=4), independent of setup results.
    float4 a0 = __ldg(pa + s);
    float4 a1 = __ldg(pa + s + 8);
    float4 b0 = __ldg(pb + s);
    float4 b1 = __ldg(pb + s + 8);

#if __CUDA_ARCH__ >= 900
    cudaGridDependencySynchronize();   // wait for setup kernel's writes
#endif

    if (!active) return;

    if (g_all_geo) {
        const float4* pc = reinterpret_cast<const float4*>(g_coef);
        float4 c0 = pc[s];
        float4 c1 = pc[s + 8];

        float sa = dot8_log(a0, a1, c0, c1);
        float sb = dot8_log(b0, b1, c0, c1);

        sa += __shfl_xor_sync(0xFFFFFFFFu, sa, 4);
        sb += __shfl_xor_sync(0xFFFFFFFFu, sb, 4);
        sa += __shfl_xor_sync(0xFFFFFFFFu, sa, 2);
        sb += __shfl_xor_sync(0xFFFFFFFFu, sb, 2);
        sa += __shfl_xor_sync(0xFFFFFFFFu, sa, 1);
        sb += __shfl_xor_sync(0xFFFFFFFFu, sb, 1);

        if (s == 0) {
            float2 o = make_float2(exp2f(sa), exp2f(sb));
            *reinterpret_cast<float2*>(out + rowA) = o;
        }
    } else {
        // Generic sequential path (unused for these inputs): leader walks rows.
        if (s == 0) {
            int rows[2] = {rowA, rowB};
#pragma unroll
            for (int q = 0; q < 2; q++) {
                const float* xr = x + (size_t)rows[q] * NCOL;
                float acc = aggregate_step(xr[0], xr[1], 0);
                for (int k = 1; k < LSTEP; k++) {
                    float z = aggregate_step(acc, xr[k + 1], k);
                    if (isnan(z)) z = g_a[k];
                    acc = z;
                }
                out[rows[q]] = acc;
            }
        }
    }
}

extern "C" void kernel_launch(void* const* d_in, const int* in_sizes, int n_in,
                              void* d_out, int out_size) {
    const float* x     = (const float*)d_in[0];
    const float* a_raw = (const float*)d_in[1];
    const float* w_raw = (const float*)d_in[2];
    float* out = (float*)d_out;

    int B = in_sizes[0] / NCOL;   // B is even for this problem (524288)

    vln_setup_kernel<<<1, 64>>>(a_raw, w_raw);

    long long total_threads = ((long long)B / 2) * 8;
    int threads = 256;
    int blocks  = (int)((total_threads + threads - 1) / threads);

    // Programmatic dependent launch: main grid begins launching while the
    // setup kernel runs; device-side cudaGridDependencySynchronize() enforces
    // the data dependency. Falls back to normal stream-order semantics.
    cudaLaunchConfig_t cfg = {};
    cfg.gridDim  = dim3((unsigned)blocks, 1, 1);
    cfg.blockDim = dim3((unsigned)threads, 1, 1);
    cfg.dynamicSmemBytes = 0;
    cfg.stream = 0;
    cudaLaunchAttribute attr[1];
    attr[0].id = cudaLaunchAttributeProgrammaticStreamSerialization;
    attr[0].val.programmaticStreamSerializationAllowed = 1;
    cfg.attrs = attr;
    cfg.numAttrs = 1;

    cudaError_t err = cudaLaunchKernelEx(&cfg, vln_main_kernel, x, out, B);
    if (err != cudaSuccess) {
        // Fallback: plain serialized launch (identical semantics).
        vln_main_kernel<<<blocks, threads>>>(x, out, B);
    }
}